// round 1
// baseline (speedup 1.0000x reference)
#include <cuda_runtime.h>
#include <math.h>

// Problem constants
#define NB    1024      // bs*T
#define NE_   64
#define NAG   16
#define HYPD  256
#define EMBD  32
#define NROWS 65536     // NB*NE_

// ---------------- scratch (device globals; no allocation) ----------------
__device__ float g_x1  [ (size_t)NROWS * HYPD      ];   //  64 MB
__device__ float g_qkv [ (size_t)NROWS * 3 * HYPD  ];   // 192 MB
__device__ float g_attn[ (size_t)NB * NAG * HYPD   ];   //  16 MB
__device__ float g_a2  [ (size_t)NB * NAG * HYPD   ];   //  16 MB
__device__ float g_w1mat[ (size_t)NB * NAG * EMBD  ];
__device__ float g_b1vec[ (size_t)NB * EMBD        ];
__device__ float g_wfvec[ (size_t)NB * EMBD        ];
__device__ float g_vvs  [ NB                       ];

// ---------------- SGEMM: C[M,N] = A[M,K] @ B[N,K]^T (+bias)(+relu) --------
// 128x128 block tile, 8x8 per thread, K-tile 8, double-buffered smem.
__global__ __launch_bounds__(256, 2)
void sgemm(const float* __restrict__ A, const float* __restrict__ Bw,
           const float* __restrict__ bias, float* __restrict__ C,
           int M, int N, int K, int relu)
{
    __shared__ float As[2][8][128];
    __shared__ float Bs[2][8][128];
    const int tid  = threadIdx.x;
    const int row  = tid >> 1;           // 0..127
    const int col4 = (tid & 1) << 2;     // 0 or 4
    const int tx   = tid & 15;
    const int ty   = tid >> 4;

    const float* Ag = A  + ((size_t)blockIdx.y * 128 + row) * K + col4;
    const float* Bg = Bw + ((size_t)blockIdx.x * 128 + row) * K + col4;

    float acc[8][8];
#pragma unroll
    for (int i = 0; i < 8; i++)
#pragma unroll
        for (int j = 0; j < 8; j++) acc[i][j] = 0.f;

    float4 a4 = *reinterpret_cast<const float4*>(Ag);
    float4 b4 = *reinterpret_cast<const float4*>(Bg);
    As[0][col4+0][row] = a4.x; As[0][col4+1][row] = a4.y;
    As[0][col4+2][row] = a4.z; As[0][col4+3][row] = a4.w;
    Bs[0][col4+0][row] = b4.x; Bs[0][col4+1][row] = b4.y;
    Bs[0][col4+2][row] = b4.z; Bs[0][col4+3][row] = b4.w;
    __syncthreads();

    const int nk = K >> 3;
    for (int kt = 0; kt < nk; ++kt) {
        const int cur = kt & 1;
        if (kt + 1 < nk) {
            a4 = *reinterpret_cast<const float4*>(Ag + (kt + 1) * 8);
            b4 = *reinterpret_cast<const float4*>(Bg + (kt + 1) * 8);
        }
#pragma unroll
        for (int k = 0; k < 8; k++) {
            float4 a0 = *reinterpret_cast<const float4*>(&As[cur][k][ty * 8]);
            float4 a1 = *reinterpret_cast<const float4*>(&As[cur][k][ty * 8 + 4]);
            float4 b0 = *reinterpret_cast<const float4*>(&Bs[cur][k][tx * 8]);
            float4 b1 = *reinterpret_cast<const float4*>(&Bs[cur][k][tx * 8 + 4]);
            float af[8] = {a0.x,a0.y,a0.z,a0.w,a1.x,a1.y,a1.z,a1.w};
            float bf[8] = {b0.x,b0.y,b0.z,b0.w,b1.x,b1.y,b1.z,b1.w};
#pragma unroll
            for (int i = 0; i < 8; i++)
#pragma unroll
                for (int j = 0; j < 8; j++)
                    acc[i][j] += af[i] * bf[j];
        }
        if (kt + 1 < nk) {
            const int nxt = cur ^ 1;
            As[nxt][col4+0][row] = a4.x; As[nxt][col4+1][row] = a4.y;
            As[nxt][col4+2][row] = a4.z; As[nxt][col4+3][row] = a4.w;
            Bs[nxt][col4+0][row] = b4.x; Bs[nxt][col4+1][row] = b4.y;
            Bs[nxt][col4+2][row] = b4.z; Bs[nxt][col4+3][row] = b4.w;
            __syncthreads();
        }
    }

    float bb[8];
#pragma unroll
    for (int j = 0; j < 8; j++)
        bb[j] = bias ? bias[blockIdx.x * 128 + tx * 8 + j] : 0.f;

#pragma unroll
    for (int i = 0; i < 8; i++) {
        size_t gm = (size_t)blockIdx.y * 128 + ty * 8 + i;
        float* cp = C + gm * N + blockIdx.x * 128 + tx * 8;
        float o[8];
#pragma unroll
        for (int j = 0; j < 8; j++) {
            float v = acc[i][j] + bb[j];
            o[j] = relu ? fmaxf(v, 0.f) : v;
        }
        *reinterpret_cast<float4*>(cp)     = make_float4(o[0], o[1], o[2], o[3]);
        *reinterpret_cast<float4*>(cp + 4) = make_float4(o[4], o[5], o[6], o[7]);
    }
}

// ---------------- per-row attention (1 CTA per batch row) -----------------
// Mask semantics from the reference: attend ONLY where agent_mask==0 AND
// entity_mask==0; rows with no valid key produce exact zeros.
__global__ __launch_bounds__(256)
void attn_kernel(const float* __restrict__ qkv, const int* __restrict__ emask,
                 float* __restrict__ attn_out)
{
    __shared__ float Qs[16][64];
    __shared__ float Kt[64][68];   // K transposed [d][k], padded
    __shared__ float Vs[64][64];
    __shared__ float Ws[16][68];   // logits -> weights
    __shared__ int   em[64];

    const int b   = blockIdx.x;
    const int tid = threadIdx.x;
    if (tid < 64) em[tid] = emask[b * 64 + tid];
    const float* qb = qkv + (size_t)b * 64 * 768;

    for (int h = 0; h < 4; ++h) {
        __syncthreads();
        // load Q [16 x 64]
        {
            int n  = tid >> 4;
            int d0 = (tid & 15) << 2;
            *reinterpret_cast<float4*>(&Qs[n][d0]) =
                *reinterpret_cast<const float4*>(qb + (size_t)n * 768 + h * 64 + d0);
        }
        // load K transposed + V [64 x 64]
        {
            int n  = tid >> 2;
            int d0 = (tid & 3) << 4;
            const float* kr = qb + (size_t)n * 768 + 256 + h * 64 + d0;
            const float* vr = qb + (size_t)n * 768 + 512 + h * 64 + d0;
#pragma unroll
            for (int j = 0; j < 4; j++) {
                float4 kv = *reinterpret_cast<const float4*>(kr + j * 4);
                Kt[d0 + j*4 + 0][n] = kv.x; Kt[d0 + j*4 + 1][n] = kv.y;
                Kt[d0 + j*4 + 2][n] = kv.z; Kt[d0 + j*4 + 3][n] = kv.w;
                *reinterpret_cast<float4*>(&Vs[n][d0 + j*4]) =
                    *reinterpret_cast<const float4*>(vr + j * 4);
            }
        }
        __syncthreads();
        // logits: thread = (qi, 4 keys)
        {
            int qi = tid >> 4;
            int k0 = (tid & 15) << 2;
            float4 acc = make_float4(0.f, 0.f, 0.f, 0.f);
#pragma unroll 8
            for (int d = 0; d < 64; ++d) {
                float  qv = Qs[qi][d];
                float4 kv = *reinterpret_cast<const float4*>(&Kt[d][k0]);
                acc.x += qv * kv.x; acc.y += qv * kv.y;
                acc.z += qv * kv.z; acc.w += qv * kv.w;
            }
            int   amq  = em[qi];
            float lg[4] = {acc.x, acc.y, acc.z, acc.w};
#pragma unroll
            for (int j = 0; j < 4; j++) {
                int kk = k0 + j;
                bool valid = (amq == 0) && (em[kk] == 0);
                Ws[qi][kk] = valid ? lg[j] * 0.125f : -1e30f;
            }
        }
        __syncthreads();
        // softmax: warp w handles rows 2w, 2w+1
        {
            int w = tid >> 5, lane = tid & 31;
            for (int r = 0; r < 2; r++) {
                int   qi = w * 2 + r;
                float v0 = Ws[qi][lane], v1 = Ws[qi][lane + 32];
                float m  = fmaxf(v0, v1);
                for (int off = 16; off; off >>= 1)
                    m = fmaxf(m, __shfl_xor_sync(0xffffffffu, m, off));
                float e0 = 0.f, e1 = 0.f, s = 1.f;
                if (m > -1e29f) {
                    e0 = expf(v0 - m); e1 = expf(v1 - m);
                    s = e0 + e1;
                    for (int off = 16; off; off >>= 1)
                        s += __shfl_xor_sync(0xffffffffu, s, off);
                }
                float inv = 1.f / s;
                Ws[qi][lane]      = e0 * inv;
                Ws[qi][lane + 32] = e1 * inv;
            }
        }
        __syncthreads();
        // AV: thread = (qi, 4 dims)
        {
            int qi = tid >> 4;
            int d0 = (tid & 15) << 2;
            float4 acc = make_float4(0.f, 0.f, 0.f, 0.f);
#pragma unroll 8
            for (int k = 0; k < 64; k++) {
                float  wv = Ws[qi][k];
                float4 vv = *reinterpret_cast<const float4*>(&Vs[k][d0]);
                acc.x += wv * vv.x; acc.y += wv * vv.y;
                acc.z += wv * vv.z; acc.w += wv * vv.w;
            }
            *reinterpret_cast<float4*>(attn_out + ((size_t)b * 16 + qi) * 256 + h * 64 + d0) = acc;
        }
    }
}

// --------- fc2 + agent-mask + mode reduction (1 CTA per batch row) --------
// mode: 0 = matrix(|x3|) -> g_w1mat, 1 = mean_a -> g_b1vec,
//       2 = mean_a -> g_wfvec, 3 = mean_{a,e} -> g_vvs
__global__ __launch_bounds__(256)
void fc2_reduce(const float* __restrict__ a2, const int* __restrict__ emask,
                const float* __restrict__ fc2w, const float* __restrict__ fc2b,
                int mode)
{
    __shared__ float a2s[16][260];
    __shared__ float red[32][17];
    __shared__ float vecs[32];
    const int b   = blockIdx.x;
    const int tid = threadIdx.x;

    for (int i = tid; i < 1024; i += 256) {           // 16 rows * 64 float4
        int a  = i >> 6;
        int c4 = (i & 63) << 2;
        *reinterpret_cast<float4*>(&a2s[a][c4]) =
            *reinterpret_cast<const float4*>(a2 + ((size_t)b * 16 + a) * 256 + c4);
    }
    __syncthreads();

    float x3v[2];
#pragma unroll
    for (int it = 0; it < 2; ++it) {
        int o = tid + it * 256;
        int a = o & 15;
        int e = o >> 4;
        float s = 0.f;
        if (emask[b * 64 + a] == 0) {
            const float* wr = fc2w + e * 256;
            float acc = 0.f;
#pragma unroll 4
            for (int kk = 0; kk < 256; ++kk) acc += a2s[a][kk] * wr[kk];
            s = acc + fc2b[e];
        }
        x3v[it] = s;
        if (mode == 0)
            g_w1mat[((size_t)b * 16 + a) * 32 + e] = fabsf(s);
    }
    if (mode != 0) {
#pragma unroll
        for (int it = 0; it < 2; ++it) {
            int o = tid + it * 256;
            red[o >> 4][o & 15] = x3v[it];
        }
        __syncthreads();
        if (tid < 32) {
            float s = 0.f;
#pragma unroll
            for (int a = 0; a < 16; a++) s += red[tid][a];
            s *= (1.f / 16.f);
            vecs[tid] = s;
            if (mode == 1)      g_b1vec[b * 32 + tid] = s;
            else if (mode == 2) g_wfvec[b * 32 + tid] = s;
        }
        __syncthreads();
        if (mode == 3 && tid == 0) {
            float s = 0.f;
            for (int e = 0; e < 32; e++) s += vecs[e];
            g_vvs[b] = s * (1.f / 32.f);
        }
    }
}

// ---------------- final mixing: 1 warp per batch row ----------------------
__global__ __launch_bounds__(256)
void mix_kernel(const float* __restrict__ qs, float* __restrict__ out)
{
    int tid = threadIdx.x;
    int b   = blockIdx.x * 8 + (tid >> 5);
    int e   = tid & 31;
    float h = g_b1vec[b * 32 + e];
#pragma unroll
    for (int a = 0; a < 16; a++)
        h += qs[b * 16 + a] * fabsf(g_w1mat[((size_t)b * 16 + a) * 32 + e]);
    h = h > 0.f ? h : expm1f(h);                    // ELU
    float val = h * fabsf(g_wfvec[b * 32 + e]);
    for (int off = 16; off; off >>= 1)
        val += __shfl_xor_sync(0xffffffffu, val, off);
    if (e == 0) out[b] = val + g_vvs[b];
}

// ---------------- launch --------------------------------------------------
extern "C" void kernel_launch(void* const* d_in, const int* in_sizes, int n_in,
                              void* d_out, int out_size)
{
    (void)in_sizes; (void)n_in; (void)out_size;
    const float* qs    = (const float*)d_in[0];
    const float* ents  = (const float*)d_in[1];
    const int*   emask = (const int*)d_in[2];

    float *x1, *qkv, *attn, *a2;
    cudaGetSymbolAddress((void**)&x1,   g_x1);
    cudaGetSymbolAddress((void**)&qkv,  g_qkv);
    cudaGetSymbolAddress((void**)&attn, g_attn);
    cudaGetSymbolAddress((void**)&a2,   g_a2);

    for (int p = 0; p < 4; p++) {
        const float* fc1w = (const float*)d_in[3 + 7*p + 0];
        const float* fc1b = (const float*)d_in[3 + 7*p + 1];
        const float* qkvw = (const float*)d_in[3 + 7*p + 2];
        const float* outw = (const float*)d_in[3 + 7*p + 3];
        const float* outb = (const float*)d_in[3 + 7*p + 4];
        const float* fc2w = (const float*)d_in[3 + 7*p + 5];
        const float* fc2b = (const float*)d_in[3 + 7*p + 6];

        // x1 = relu(E @ fc1^T + b)          [65536, 256]
        sgemm<<<dim3(2, 512), 256>>>(ents, fc1w, fc1b, x1, NROWS, 256, 128, 1);
        // qkv = x1 @ qkv_w^T                [65536, 768]
        sgemm<<<dim3(6, 512), 256>>>(x1, qkvw, nullptr, qkv, NROWS, 768, 256, 0);
        // attention                          [16384, 256]
        attn_kernel<<<NB, 256>>>(qkv, emask, attn);
        // a2 = attn @ out_w^T + out_b        [16384, 256]
        sgemm<<<dim3(2, 128), 256>>>(attn, outw, outb, a2, NB * NAG, 256, 256, 0);
        // x3 = mask(a2 @ fc2^T + b) + mode reduction
        fc2_reduce<<<NB, 256>>>(a2, emask, fc2w, fc2b, p);
    }
    mix_kernel<<<NB / 8, 256>>>(qs, (float*)d_out);
}

// round 3
// speedup vs baseline: 1.6482x; 1.6482x over previous
#include <cuda_runtime.h>
#include <cuda_bf16.h>
#include <math.h>
#include <stdint.h>

// Problem constants
#define NB    1024      // bs*T
#define NAG   16
#define HYPD  256
#define EMBD  32
#define NROWS 65536     // NB*64

// ---------------- scratch (device globals; no allocation) ----------------
__device__ float g_x1  [4ull * NROWS * HYPD     ];   // 256 MB
__device__ float g_qkv [4ull * NROWS * 3 * HYPD ];   // 768 MB
__device__ float g_attn[4ull * NB * NAG * HYPD  ];
__device__ float g_a2  [4ull * NB * NAG * HYPD  ];
__device__ float g_w1mat[(size_t)NB * NAG * EMBD];
__device__ float g_b1vec[(size_t)NB * EMBD      ];
__device__ float g_wfvec[(size_t)NB * EMBD      ];
__device__ float g_vvs  [NB                     ];

// ================= helpers ================================================
__device__ __forceinline__ uint32_t smem_u32(const void* p) {
    uint32_t a;
    asm("{ .reg .u64 t; cvta.to.shared.u64 t, %1; cvt.u32.u64 %0, t; }"
        : "=r"(a) : "l"(p));
    return a;
}

// fp32 pair -> packed bf16x2 (hi) + packed bf16x2 (residual lo)
__device__ __forceinline__ void cvt_pair(float a, float b, uint32_t& hi, uint32_t& lo) {
    asm("cvt.rn.bf16x2.f32 %0, %1, %2;" : "=r"(hi) : "f"(b), "f"(a)); // low16=a, high16=b
    float ra = a - __uint_as_float(hi << 16);
    float rb = b - __uint_as_float(hi & 0xffff0000u);
    asm("cvt.rn.bf16x2.f32 %0, %1, %2;" : "=r"(lo) : "f"(rb), "f"(ra));
}

__device__ __forceinline__ void ldm_x4(uint32_t* r, uint32_t addr) {
    asm volatile("ldmatrix.sync.aligned.m8n8.x4.shared.b16 {%0,%1,%2,%3}, [%4];"
                 : "=r"(r[0]), "=r"(r[1]), "=r"(r[2]), "=r"(r[3]) : "r"(addr));
}

__device__ __forceinline__ void mma_bf16(float* d, const uint32_t* a,
                                         uint32_t b0, uint32_t b1) {
    asm volatile(
        "mma.sync.aligned.m16n8k16.row.col.f32.bf16.bf16.f32 "
        "{%0,%1,%2,%3},{%4,%5,%6,%7},{%8,%9},{%0,%1,%2,%3};"
        : "+f"(d[0]), "+f"(d[1]), "+f"(d[2]), "+f"(d[3])
        : "r"(a[0]), "r"(a[1]), "r"(a[2]), "r"(a[3]), "r"(b0), "r"(b1));
}

// =============== batched tensor-core GEMM =================================
// C_z[M,N] = A_z[M,K] @ B_z[N,K]^T (+bias)(+relu), z = blockIdx.z param set.
// fp32 in gmem; bf16 hi/lo split in-kernel; 3-MMA compensated accumulate.
// CTA tile 128x128, Ktile 32, double-buffered smem, reg prefetch.
struct GemmBatch {
    const float* A[4];
    const float* B[4];
    const float* bias[4];
    float*       C[4];
};

#define SROW_B     80                       // padded row: 32 bf16 = 64B data + 16B pad
#define TILE_B     (128 * SROW_B)           // 10240 bytes per operand tile
#define BUF_B      (4 * TILE_B)             // Ah, Al, Bh, Bl
#define GEMM_SMEM  (2 * BUF_B)              // 81920

__global__ void __launch_bounds__(256) gemm_mma(GemmBatch args, int N, int K, int relu)
{
    extern __shared__ char smem[];
    const int z = blockIdx.z;
    const float* __restrict__ A    = args.A[z];
    const float* __restrict__ Bw   = args.B[z];
    const float* __restrict__ bias = args.bias[z];
    float* __restrict__ C          = args.C[z];

    const int tid  = threadIdx.x;
    const int lane = tid & 31;
    const int wid  = tid >> 5;
    const int wm   = wid & 1;          // warp row (2)
    const int wn   = wid >> 1;         // warp col (4)

    const float* Abase = A  + ((size_t)blockIdx.y * 128) * K;
    const float* Bbase = Bw + ((size_t)blockIdx.x * 128) * K;

    // loader: 4 chunks each for A and B; chunk -> (row, 4 consecutive k)
    int rows[4], kcs[4];
#pragma unroll
    for (int i = 0; i < 4; i++) {
        int c = tid + i * 256;
        rows[i] = c >> 3;
        kcs[i]  = c & 7;
    }

    float acc[4][4][4];
#pragma unroll
    for (int a = 0; a < 4; a++)
#pragma unroll
        for (int b = 0; b < 4; b++)
#pragma unroll
            for (int c = 0; c < 4; c++) acc[a][b][c] = 0.f;

    const uint32_t sbase = smem_u32(smem);
    const int nk = K >> 5;

    float4 pf[8];
    // prologue: load ktile 0
#pragma unroll
    for (int i = 0; i < 4; i++) {
        pf[i]     = *reinterpret_cast<const float4*>(Abase + (size_t)rows[i] * K + kcs[i] * 4);
        pf[4 + i] = *reinterpret_cast<const float4*>(Bbase + (size_t)rows[i] * K + kcs[i] * 4);
    }
    {   // convert + store buffer 0
        char* buf = smem;
#pragma unroll
        for (int i = 0; i < 8; i++) {
            uint32_t h0, l0, h1, l1;
            cvt_pair(pf[i].x, pf[i].y, h0, l0);
            cvt_pair(pf[i].z, pf[i].w, h1, l1);
            uint32_t off = (uint32_t)rows[i & 3] * SROW_B + kcs[i & 3] * 8;
            char* base = buf + (i < 4 ? 0 : 2 * TILE_B) + off;
            *reinterpret_cast<uint2*>(base)          = make_uint2(h0, h1);
            *reinterpret_cast<uint2*>(base + TILE_B) = make_uint2(l0, l1);
        }
    }
    __syncthreads();

    for (int kt = 0; kt < nk; kt++) {
        const int b = kt & 1;
        // prefetch next ktile to regs
        if (kt + 1 < nk) {
            const int ko = (kt + 1) * 32;
#pragma unroll
            for (int i = 0; i < 4; i++) {
                pf[i]     = *reinterpret_cast<const float4*>(Abase + (size_t)rows[i] * K + ko + kcs[i] * 4);
                pf[4 + i] = *reinterpret_cast<const float4*>(Bbase + (size_t)rows[i] * K + ko + kcs[i] * 4);
            }
        }
        // MMA on buffer b
        {
            const uint32_t sA  = sbase + b * BUF_B;
            const uint32_t sAl = sA + TILE_B;
            const uint32_t sB  = sA + 2 * TILE_B;
            const uint32_t sBl = sA + 3 * TILE_B;
            const int lrow  = lane & 15;
            const int khalf = lane >> 4;
#pragma unroll
            for (int ks = 0; ks < 2; ks++) {
                const uint32_t koff = ks * 32 + khalf * 16;
                uint32_t ah[4][4], bh[2][4];
#pragma unroll
                for (int mb = 0; mb < 4; mb++)
                    ldm_x4(ah[mb], sA + (wm * 64 + mb * 16 + lrow) * SROW_B + koff);
#pragma unroll
                for (int nb = 0; nb < 2; nb++)
                    ldm_x4(bh[nb], sB + (wn * 32 + nb * 16 + lrow) * SROW_B + koff);
#pragma unroll
                for (int mb = 0; mb < 4; mb++)
#pragma unroll
                    for (int nb = 0; nb < 4; nb++)
                        mma_bf16(acc[mb][nb], ah[mb],
                                 bh[nb >> 1][nb & 1], bh[nb >> 1][(nb & 1) + 2]);
                uint32_t bl[2][4];
#pragma unroll
                for (int nb = 0; nb < 2; nb++)
                    ldm_x4(bl[nb], sBl + (wn * 32 + nb * 16 + lrow) * SROW_B + koff);
#pragma unroll
                for (int mb = 0; mb < 4; mb++)
#pragma unroll
                    for (int nb = 0; nb < 4; nb++)
                        mma_bf16(acc[mb][nb], ah[mb],
                                 bl[nb >> 1][nb & 1], bl[nb >> 1][(nb & 1) + 2]);
                uint32_t al[4][4];
#pragma unroll
                for (int mb = 0; mb < 4; mb++)
                    ldm_x4(al[mb], sAl + (wm * 64 + mb * 16 + lrow) * SROW_B + koff);
#pragma unroll
                for (int mb = 0; mb < 4; mb++)
#pragma unroll
                    for (int nb = 0; nb < 4; nb++)
                        mma_bf16(acc[mb][nb], al[mb],
                                 bh[nb >> 1][nb & 1], bh[nb >> 1][(nb & 1) + 2]);
            }
        }
        // convert + store next buffer
        if (kt + 1 < nk) {
            char* buf = smem + (b ^ 1) * BUF_B;
#pragma unroll
            for (int i = 0; i < 8; i++) {
                uint32_t h0, l0, h1, l1;
                cvt_pair(pf[i].x, pf[i].y, h0, l0);
                cvt_pair(pf[i].z, pf[i].w, h1, l1);
                uint32_t off = (uint32_t)rows[i & 3] * SROW_B + kcs[i & 3] * 8;
                char* base = buf + (i < 4 ? 0 : 2 * TILE_B) + off;
                *reinterpret_cast<uint2*>(base)          = make_uint2(h0, h1);
                *reinterpret_cast<uint2*>(base + TILE_B) = make_uint2(l0, l1);
            }
        }
        __syncthreads();
    }

    // epilogue
    const int m0 = blockIdx.y * 128 + wm * 64 + (lane >> 2);
#pragma unroll
    for (int nb = 0; nb < 4; nb++) {
        const int col = blockIdx.x * 128 + wn * 32 + nb * 8 + (lane & 3) * 2;
        const float b0 = bias ? bias[col]     : 0.f;
        const float b1 = bias ? bias[col + 1] : 0.f;
#pragma unroll
        for (int mb = 0; mb < 4; mb++) {
            float v0 = acc[mb][nb][0] + b0;
            float v1 = acc[mb][nb][1] + b1;
            float v2 = acc[mb][nb][2] + b0;
            float v3 = acc[mb][nb][3] + b1;
            if (relu) {
                v0 = fmaxf(v0, 0.f); v1 = fmaxf(v1, 0.f);
                v2 = fmaxf(v2, 0.f); v3 = fmaxf(v3, 0.f);
            }
            const int r = m0 + mb * 16;
            *reinterpret_cast<float2*>(C + (size_t)r * N + col)       = make_float2(v0, v1);
            *reinterpret_cast<float2*>(C + (size_t)(r + 8) * N + col) = make_float2(v2, v3);
        }
    }
}

// ---------------- per-row attention (1 CTA per (batch row, param)) --------
struct AttnBatch { const float* qkv[4]; float* attn[4]; };

__global__ __launch_bounds__(256)
void attn_kernel(AttnBatch args, const int* __restrict__ emask)
{
    __shared__ float Qs[16][64];
    __shared__ float Kt[64][68];
    __shared__ float Vs[64][64];
    __shared__ float Ws[16][68];
    __shared__ int   em[64];

    const int b   = blockIdx.x;
    const int z   = blockIdx.z;
    const int tid = threadIdx.x;
    const float* __restrict__ qkv = args.qkv[z];
    float* __restrict__ attn_out  = args.attn[z];

    if (tid < 64) em[tid] = emask[b * 64 + tid];
    const float* qb = qkv + (size_t)b * 64 * 768;

    for (int h = 0; h < 4; ++h) {
        __syncthreads();
        {
            int n  = tid >> 4;
            int d0 = (tid & 15) << 2;
            *reinterpret_cast<float4*>(&Qs[n][d0]) =
                *reinterpret_cast<const float4*>(qb + (size_t)n * 768 + h * 64 + d0);
        }
        {
            int n  = tid >> 2;
            int d0 = (tid & 3) << 4;
            const float* kr = qb + (size_t)n * 768 + 256 + h * 64 + d0;
            const float* vr = qb + (size_t)n * 768 + 512 + h * 64 + d0;
#pragma unroll
            for (int j = 0; j < 4; j++) {
                float4 kv = *reinterpret_cast<const float4*>(kr + j * 4);
                Kt[d0 + j*4 + 0][n] = kv.x; Kt[d0 + j*4 + 1][n] = kv.y;
                Kt[d0 + j*4 + 2][n] = kv.z; Kt[d0 + j*4 + 3][n] = kv.w;
                *reinterpret_cast<float4*>(&Vs[n][d0 + j*4]) =
                    *reinterpret_cast<const float4*>(vr + j * 4);
            }
        }
        __syncthreads();
        {
            int qi = tid >> 4;
            int k0 = (tid & 15) << 2;
            float4 acc = make_float4(0.f, 0.f, 0.f, 0.f);
#pragma unroll 8
            for (int d = 0; d < 64; ++d) {
                float  qv = Qs[qi][d];
                float4 kv = *reinterpret_cast<const float4*>(&Kt[d][k0]);
                acc.x += qv * kv.x; acc.y += qv * kv.y;
                acc.z += qv * kv.z; acc.w += qv * kv.w;
            }
            int   amq  = em[qi];
            float lg[4] = {acc.x, acc.y, acc.z, acc.w};
#pragma unroll
            for (int j = 0; j < 4; j++) {
                int kk = k0 + j;
                bool valid = (amq == 0) && (em[kk] == 0);
                Ws[qi][kk] = valid ? lg[j] * 0.125f : -1e30f;
            }
        }
        __syncthreads();
        {
            int w = tid >> 5, lane = tid & 31;
            for (int r = 0; r < 2; r++) {
                int   qi = w * 2 + r;
                float v0 = Ws[qi][lane], v1 = Ws[qi][lane + 32];
                float m  = fmaxf(v0, v1);
                for (int off = 16; off; off >>= 1)
                    m = fmaxf(m, __shfl_xor_sync(0xffffffffu, m, off));
                float e0 = 0.f, e1 = 0.f, s = 1.f;
                if (m > -1e29f) {
                    e0 = expf(v0 - m); e1 = expf(v1 - m);
                    s = e0 + e1;
                    for (int off = 16; off; off >>= 1)
                        s += __shfl_xor_sync(0xffffffffu, s, off);
                }
                float inv = 1.f / s;
                Ws[qi][lane]      = e0 * inv;
                Ws[qi][lane + 32] = e1 * inv;
            }
        }
        __syncthreads();
        {
            int qi = tid >> 4;
            int d0 = (tid & 15) << 2;
            float4 acc = make_float4(0.f, 0.f, 0.f, 0.f);
#pragma unroll 8
            for (int k = 0; k < 64; k++) {
                float  wv = Ws[qi][k];
                float4 vv = *reinterpret_cast<const float4*>(&Vs[k][d0]);
                acc.x += wv * vv.x; acc.y += wv * vv.y;
                acc.z += wv * vv.z; acc.w += wv * vv.w;
            }
            *reinterpret_cast<float4*>(attn_out + ((size_t)b * 16 + qi) * 256 + h * 64 + d0) = acc;
        }
    }
}

// --------- fc2 + agent-mask + mode reduction (z = mode = param set) -------
struct Fc2Batch { const float* a2[4]; const float* w[4]; const float* bvec[4]; };

__global__ __launch_bounds__(256)
void fc2_reduce(Fc2Batch args, const int* __restrict__ emask)
{
    __shared__ float a2s[16][260];
    __shared__ float red[32][17];
    __shared__ float vecs[32];
    const int b    = blockIdx.x;
    const int mode = blockIdx.z;
    const int tid  = threadIdx.x;
    const float* __restrict__ a2   = args.a2[mode];
    const float* __restrict__ fc2w = args.w[mode];
    const float* __restrict__ fc2b = args.bvec[mode];

    for (int i = tid; i < 1024; i += 256) {
        int a  = i >> 6;
        int c4 = (i & 63) << 2;
        *reinterpret_cast<float4*>(&a2s[a][c4]) =
            *reinterpret_cast<const float4*>(a2 + ((size_t)b * 16 + a) * 256 + c4);
    }
    __syncthreads();

    float x3v[2];
#pragma unroll
    for (int it = 0; it < 2; ++it) {
        int o = tid + it * 256;
        int a = o & 15;
        int e = o >> 4;
        float s = 0.f;
        if (emask[b * 64 + a] == 0) {
            const float* wr = fc2w + e * 256;
            float acc = 0.f;
#pragma unroll 4
            for (int kk = 0; kk < 256; ++kk) acc += a2s[a][kk] * wr[kk];
            s = acc + fc2b[e];
        }
        x3v[it] = s;
        if (mode == 0)
            g_w1mat[((size_t)b * 16 + a) * 32 + e] = fabsf(s);
    }
    if (mode != 0) {
#pragma unroll
        for (int it = 0; it < 2; ++it) {
            int o = tid + it * 256;
            red[o >> 4][o & 15] = x3v[it];
        }
        __syncthreads();
        if (tid < 32) {
            float s = 0.f;
#pragma unroll
            for (int a = 0; a < 16; a++) s += red[tid][a];
            s *= (1.f / 16.f);
            vecs[tid] = s;
            if (mode == 1)      g_b1vec[b * 32 + tid] = s;
            else if (mode == 2) g_wfvec[b * 32 + tid] = s;
        }
        __syncthreads();
        if (mode == 3 && tid == 0) {
            float s = 0.f;
            for (int e = 0; e < 32; e++) s += vecs[e];
            g_vvs[b] = s * (1.f / 32.f);
        }
    }
}

// ---------------- final mixing: 1 warp per batch row ----------------------
__global__ __launch_bounds__(256)
void mix_kernel(const float* __restrict__ qs, float* __restrict__ out)
{
    int tid = threadIdx.x;
    int b   = blockIdx.x * 8 + (tid >> 5);
    int e   = tid & 31;
    float h = g_b1vec[b * 32 + e];
#pragma unroll
    for (int a = 0; a < 16; a++)
        h += qs[b * 16 + a] * fabsf(g_w1mat[((size_t)b * 16 + a) * 32 + e]);
    h = h > 0.f ? h : expm1f(h);
    float val = h * fabsf(g_wfvec[b * 32 + e]);
    for (int off = 16; off; off >>= 1)
        val += __shfl_xor_sync(0xffffffffu, val, off);
    if (e == 0) out[b] = val + g_vvs[b];
}

// ---------------- launch --------------------------------------------------
extern "C" void kernel_launch(void* const* d_in, const int* in_sizes, int n_in,
                              void* d_out, int out_size)
{
    (void)in_sizes; (void)n_in; (void)out_size;
    const float* qs    = (const float*)d_in[0];
    const float* ents  = (const float*)d_in[1];
    const int*   emask = (const int*)d_in[2];

    float *x1, *qkv, *attn, *a2;
    cudaGetSymbolAddress((void**)&x1,   g_x1);
    cudaGetSymbolAddress((void**)&qkv,  g_qkv);
    cudaGetSymbolAddress((void**)&attn, g_attn);
    cudaGetSymbolAddress((void**)&a2,   g_a2);

    static bool attr_set = false;
    if (!attr_set) {
        cudaFuncSetAttribute(gemm_mma, cudaFuncAttributeMaxDynamicSharedMemorySize, GEMM_SMEM);
        attr_set = true;
    }

    GemmBatch g1, g2, g3;
    AttnBatch ab;
    Fc2Batch  fb;
    for (int p = 0; p < 4; p++) {
        const float* fc1w = (const float*)d_in[3 + 7*p + 0];
        const float* fc1b = (const float*)d_in[3 + 7*p + 1];
        const float* qkvw = (const float*)d_in[3 + 7*p + 2];
        const float* outw = (const float*)d_in[3 + 7*p + 3];
        const float* outb = (const float*)d_in[3 + 7*p + 4];
        const float* fc2w = (const float*)d_in[3 + 7*p + 5];
        const float* fc2b = (const float*)d_in[3 + 7*p + 6];

        float* x1p   = x1   + (size_t)p * NROWS * HYPD;
        float* qkvp  = qkv  + (size_t)p * NROWS * 3 * HYPD;
        float* attnp = attn + (size_t)p * NB * NAG * HYPD;
        float* a2p   = a2   + (size_t)p * NB * NAG * HYPD;

        g1.A[p] = ents;  g1.B[p] = fc1w; g1.bias[p] = fc1b;    g1.C[p] = x1p;
        g2.A[p] = x1p;   g2.B[p] = qkvw; g2.bias[p] = nullptr; g2.C[p] = qkvp;
        g3.A[p] = attnp; g3.B[p] = outw; g3.bias[p] = outb;    g3.C[p] = a2p;
        ab.qkv[p] = qkvp; ab.attn[p] = attnp;
        fb.a2[p] = a2p;   fb.w[p] = fc2w; fb.bvec[p] = fc2b;
    }

    // fc1:  x1 = relu(E @ fc1^T + b)   [65536, 256], K=128, all 4 params
    gemm_mma<<<dim3(2, 512, 4), 256, GEMM_SMEM>>>(g1, 256, 128, 1);
    // qkv = x1 @ qkv_w^T               [65536, 768], K=256
    gemm_mma<<<dim3(6, 512, 4), 256, GEMM_SMEM>>>(g2, 768, 256, 0);
    // attention                         [16384, 256] per param
    attn_kernel<<<dim3(NB, 1, 4), 256>>>(ab, emask);
    // a2 = attn @ out_w^T + out_b       [16384, 256], K=256
    gemm_mma<<<dim3(2, 128, 4), 256, GEMM_SMEM>>>(g3, 256, 256, 0);
    // fc2 + mask + mode reductions
    fc2_reduce<<<dim3(NB, 1, 4), 256>>>(fb, emask);
    mix_kernel<<<NB / 8, 256>>>(qs, (float*)d_out);
}